// round 12
// baseline (speedup 1.0000x reference)
#include <cuda_runtime.h>

#define B_   16
#define C_   384
#define H_   56
#define W_   56
#define HW_  3136
#define NHW_ 50176
#define TOT_ 19267584
#define KL   31
#define PL   15
#define KS   5
#define TS   86        // 56 + 2*15
#define STR  90        // even stride, gcd(90,32)=2 -> conflict-free float2 rows
#define WIDE 14        // output columns per thread
#define NTHR 224       // 56 rows x 4 strips -- every lane works
#define TILE_PAD (TS * STR)   // 7740, multiple of 4

// Scratch (allocation-free contract: __device__ globals)
__device__ float g_yl[TOT_];
__device__ float g_ys[TOT_];
__device__ float g_acc[C_ * 4];   // per channel: sumL, sqL, sumS, sqS
__device__ float g_prm[C_ * 3];   // per channel: aL, aS, bias

__global__ void k_zero() {
    int i = blockIdx.x * blockDim.x + threadIdx.x;
    if (i < C_ * 4) g_acc[i] = 0.f;
}

// One 31-tap kernel row: chunked double-buffered weights, 16-slot float2 window.
// FUSE=1 rows (i=13..17) also accumulate the 5x5 conv at taps 13..17 using the
// SAME window operands (tile[row+i][col0+j+t]) -- zero extra loads.
template<int FUSE>
__device__ __forceinline__ void conv_row(const float* __restrict__ xr,
                                         const float4* __restrict__ wrow,
                                         const float* __restrict__ wsrow,
                                         float* __restrict__ accL,
                                         float* __restrict__ accS) {
    float wsr[5];
    if (FUSE) {
        #pragma unroll
        for (int k = 0; k < 5; k++) wsr[k] = wsrow[k];
    }

    float xw[16];
    #pragma unroll
    for (int u = 0; u < 8; u++) {
        float2 v = *(const float2*)&xr[2 * u];
        xw[2*u] = v.x; xw[2*u+1] = v.y;
    }

    float wb[8];                                  // two 4-weight chunks
    { float4 t4 = wrow[0]; wb[0]=t4.x; wb[1]=t4.y; wb[2]=t4.z; wb[3]=t4.w; }

    #pragma unroll
    for (int jc = 0; jc < 8; jc++) {
        if (jc < 7) {                             // prefetch next chunk (4 taps ahead)
            float4 t4 = wrow[jc + 1];
            const int o = ((jc + 1) & 1) * 4;
            wb[o]=t4.x; wb[o+1]=t4.y; wb[o+2]=t4.z; wb[o+3]=t4.w;
        }
        #pragma unroll
        for (int jj = 0; jj < 4; jj++) {
            const int j = jc * 4 + jj;
            if (j >= KL) continue;                // compile-time (only j=31)
            const float wv = wb[(jc & 1) * 4 + jj];
            #pragma unroll
            for (int t = 0; t < WIDE; t++)
                accL[t] = fmaf(xw[(j + t) & 15], wv, accL[t]);
            if (FUSE && j >= 13 && j <= 17) {     // fused 5x5 taps, same operands
                const float sv = wsr[j - 13];
                #pragma unroll
                for (int t = 0; t < WIDE; t++)
                    accS[t] = fmaf(xw[(j + t) & 15], sv, accS[t]);
            }
            if ((j & 1) && j <= 27) {             // paired window refill (even addr)
                float2 v = *(const float2*)&xr[j + 15];
                xw[(j + 15) & 15] = v.x;
                xw[(j + 16) & 15] = v.y;
            }
        }
    }
}

__global__ __launch_bounds__(NTHR, 4) void k_conv(const float* __restrict__ x,
                                                  const float* __restrict__ wl_g,
                                                  const float* __restrict__ ws_g) {
    __shared__ __align__(16) float tile[TILE_PAD];
    __shared__ __align__(16) float wlp[KL * 32];   // weight rows padded to 32
    __shared__ float ws[32];
    __shared__ float red[7 * 4];

    const int blk = blockIdx.x;          // n*C + c
    const int c   = blk % C_;
    const int tid = threadIdx.x;
    const float* img = x + (size_t)blk * HW_;

    const int row   = tid % 56;          // output row / interior row
    const int strip = tid / 56;          // 0..3
    const int col0  = strip * WIDE;      // 0, 14, 28, 42 (all even)

    // ---- phase 1: zero full padded tile (float4), load weights ----
    #pragma unroll
    for (int u = 0; u < TILE_PAD / 4; u += NTHR) {
        int idx = u + tid;
        if (idx < TILE_PAD / 4) ((float4*)tile)[idx] = make_float4(0.f, 0.f, 0.f, 0.f);
    }
    for (int idx = tid; idx < KL * 32; idx += NTHR) {
        int i = idx >> 5, j = idx & 31;
        wlp[idx] = (j < KL) ? wl_g[c * KL * KL + i * KL + j] : 0.f;
    }
    if (tid < KS * KS) ws[tid] = ws_g[c * KS * KS + tid];
    __syncthreads();

    // ---- phase 2: interior load, exact fit: thread = (row, 14-col strip) ----
    {
        const float* src = img + row * W_ + col0;   // even offset -> 8B aligned
        float* dst = &tile[(row + PL) * STR + PL + col0];
        #pragma unroll
        for (int t = 0; t < WIDE; t += 2) {
            float2 v = *(const float2*)&src[t];
            dst[t]     = v.x;
            dst[t + 1] = v.y;
        }
    }
    __syncthreads();

    const size_t ob = (size_t)blk * HW_ + (size_t)row * W_ + col0;
    float sL = 0.f, qL = 0.f, sS = 0.f, qS = 0.f;

    // ---- fused 31x31 + 5x5 depthwise conv ----
    {
        float accL[WIDE], accS[WIDE];
        #pragma unroll
        for (int t = 0; t < WIDE; t++) { accL[t] = 0.f; accS[t] = 0.f; }

        #pragma unroll 1
        for (int i = 0; i < 13; i++)
            conv_row<0>(&tile[(row + i) * STR + col0],
                        (const float4*)&wlp[i * 32], ws, accL, accS);
        #pragma unroll 1
        for (int i = 13; i < 18; i++)
            conv_row<1>(&tile[(row + i) * STR + col0],
                        (const float4*)&wlp[i * 32], &ws[(i - 13) * KS], accL, accS);
        #pragma unroll 1
        for (int i = 18; i < KL; i++)
            conv_row<0>(&tile[(row + i) * STR + col0],
                        (const float4*)&wlp[i * 32], ws, accL, accS);

        #pragma unroll
        for (int t = 0; t < WIDE; t += 2) {
            *(float2*)&g_yl[ob + t] = make_float2(accL[t], accL[t+1]);
            *(float2*)&g_ys[ob + t] = make_float2(accS[t], accS[t+1]);
        }
        #pragma unroll
        for (int t = 0; t < WIDE; t++) {
            sL += accL[t]; qL = fmaf(accL[t], accL[t], qL);
            sS += accS[t]; qS = fmaf(accS[t], accS[t], qS);
        }
    }

    // ---- block reduction of the 4 stats (7 warps) ----
    #pragma unroll
    for (int o = 16; o; o >>= 1) {
        sL += __shfl_down_sync(0xffffffffu, sL, o);
        qL += __shfl_down_sync(0xffffffffu, qL, o);
        sS += __shfl_down_sync(0xffffffffu, sS, o);
        qS += __shfl_down_sync(0xffffffffu, qS, o);
    }
    const int lane = tid & 31, wpid = tid >> 5;
    if (lane == 0) { red[wpid*4+0]=sL; red[wpid*4+1]=qL; red[wpid*4+2]=sS; red[wpid*4+3]=qS; }
    __syncthreads();
    if (tid < 4) {
        float v = 0.f;
        #pragma unroll
        for (int ww = 0; ww < 7; ww++) v += red[ww * 4 + tid];
        atomicAdd(&g_acc[c * 4 + tid], v);
    }
}

__global__ void k_stats(const float* __restrict__ gL, const float* __restrict__ bL,
                        const float* __restrict__ gS, const float* __restrict__ bS) {
    int c = blockIdx.x * blockDim.x + threadIdx.x;
    if (c >= C_) return;
    const float inv_n = 1.f / (float)NHW_;
    float mL = g_acc[c*4+0] * inv_n;
    float vL = g_acc[c*4+1] * inv_n - mL * mL;
    float aL = gL[c] * rsqrtf(vL + 1e-5f);
    float mS = g_acc[c*4+2] * inv_n;
    float vS = g_acc[c*4+3] * inv_n - mS * mS;
    float aS = gS[c] * rsqrtf(vS + 1e-5f);
    g_prm[c]        = aL;
    g_prm[C_ + c]   = aS;
    g_prm[2*C_ + c] = bL[c] - mL * aL + bS[c] - mS * aS;
}

__global__ __launch_bounds__(256) void k_out(float* __restrict__ out) {
    int i = blockIdx.x * blockDim.x + threadIdx.x;
    if (i >= TOT_ / 4) return;
    int e = i * 4;
    int c = (e / HW_) % C_;          // HW_ divisible by 4 -> channel constant in float4
    float aL = g_prm[c], aS = g_prm[C_ + c], bb = g_prm[2*C_ + c];
    float4 l = ((const float4*)g_yl)[i];
    float4 s = ((const float4*)g_ys)[i];
    float4 o;
    o.x = fmaf(aL, l.x, fmaf(aS, s.x, bb));
    o.y = fmaf(aL, l.y, fmaf(aS, s.y, bb));
    o.z = fmaf(aL, l.z, fmaf(aS, s.z, bb));
    o.w = fmaf(aL, l.w, fmaf(aS, s.w, bb));
    ((float4*)out)[i] = o;
}

extern "C" void kernel_launch(void* const* d_in, const int* in_sizes, int n_in,
                              void* d_out, int out_size) {
    const float* x  = (const float*)d_in[0];
    const float* wl = (const float*)d_in[1];
    const float* gl = (const float*)d_in[2];
    const float* bl = (const float*)d_in[3];
    const float* ws = (const float*)d_in[4];
    const float* gs = (const float*)d_in[5];
    const float* bs = (const float*)d_in[6];

    k_zero<<<6, 256>>>();
    k_conv<<<B_ * C_, NTHR>>>(x, wl, ws);
    k_stats<<<2, 192>>>(gl, bl, gs, bs);
    k_out<<<(TOT_ / 4 + 255) / 256, 256>>>((float*)d_out);
}

// round 15
// speedup vs baseline: 1.0217x; 1.0217x over previous
#include <cuda_runtime.h>

#define B_   16
#define C_   384
#define H_   56
#define W_   56
#define HW_  3136
#define NHW_ 50176
#define TOT_ 19267584
#define KL   31
#define PL   15
#define KS   5
#define TS   86        // 56 + 2*15
#define STR  90        // even stride, gcd(90,32)=2 -> conflict-free float2 rows
#define WIDE 14        // output columns per thread
#define NTHR 224       // 56 rows x 4 strips -- every lane works
#define TILE_PAD (TS * STR)   // 7740, multiple of 4

// Scratch (allocation-free contract: __device__ globals)
__device__ float g_yl[TOT_];
__device__ float g_ys[TOT_];
__device__ float g_acc[C_ * 4];   // per channel: sumL, sqL, sumS, sqS
__device__ float g_prm[C_ * 3];   // per channel: aL, aS, bias

__global__ void k_zero() {
    int i = blockIdx.x * blockDim.x + threadIdx.x;
    if (i < C_ * 4) g_acc[i] = 0.f;
}

// R11 main row body: A/B half-hoisted weights + 16-slot float2-fed window.
__device__ __forceinline__ void conv_row_main(const float* __restrict__ xr,
                                              const float4* __restrict__ wrow,
                                              float* __restrict__ accL) {
    float wregA[16];
    #pragma unroll
    for (int u = 0; u < 4; u++) {
        float4 t4 = wrow[u];
        wregA[4*u]   = t4.x; wregA[4*u+1] = t4.y;
        wregA[4*u+2] = t4.z; wregA[4*u+3] = t4.w;
    }

    float xw[16];
    #pragma unroll
    for (int u = 0; u < 8; u++) {
        float2 v = *(const float2*)&xr[2 * u];
        xw[2*u] = v.x; xw[2*u+1] = v.y;
    }

    #pragma unroll
    for (int j = 0; j < 12; j++) {
        const float wv = wregA[j];
        #pragma unroll
        for (int t = 0; t < WIDE; t++)
            accL[t] = fmaf(xw[(j + t) & 15], wv, accL[t]);
        if (j & 1) {
            float2 v = *(const float2*)&xr[j + 15];
            xw[(j + 15) & 15] = v.x;
            xw[(j + 16) & 15] = v.y;
        }
    }

    float wregB[16];
    #pragma unroll
    for (int u = 0; u < 4; u++) {
        float4 t4 = wrow[4 + u];
        wregB[4*u]   = t4.x; wregB[4*u+1] = t4.y;
        wregB[4*u+2] = t4.z; wregB[4*u+3] = t4.w;
    }

    #pragma unroll
    for (int j = 12; j < 16; j++) {
        const float wv = wregA[j];
        #pragma unroll
        for (int t = 0; t < WIDE; t++)
            accL[t] = fmaf(xw[(j + t) & 15], wv, accL[t]);
        if (j & 1) {
            float2 v = *(const float2*)&xr[j + 15];
            xw[(j + 15) & 15] = v.x;
            xw[(j + 16) & 15] = v.y;
        }
    }

    #pragma unroll
    for (int j = 16; j < KL; j++) {
        const float wv = wregB[j - 16];
        #pragma unroll
        for (int t = 0; t < WIDE; t++)
            accL[t] = fmaf(xw[(j + t) & 15], wv, accL[t]);
        if ((j & 1) && j <= 27) {
            float2 v = *(const float2*)&xr[j + 15];
            xw[(j + 15) & 15] = v.x;
            xw[(j + 16) & 15] = v.y;
        }
    }
}

// Fused row body (i = 13..17): scalar per-tap weight LDS (low reg pressure),
// dual-accumulates the 5x5 conv at taps 13..17 from the SAME window registers.
__device__ __forceinline__ void conv_row_fuse(const float* __restrict__ xr,
                                              const float* __restrict__ wrow,
                                              const float* __restrict__ wsrow,
                                              float* __restrict__ accL,
                                              float* __restrict__ accS) {
    float wsr[5];
    #pragma unroll
    for (int k = 0; k < 5; k++) wsr[k] = wsrow[k];

    float xw[16];
    #pragma unroll
    for (int u = 0; u < 8; u++) {
        float2 v = *(const float2*)&xr[2 * u];
        xw[2*u] = v.x; xw[2*u+1] = v.y;
    }

    #pragma unroll
    for (int j = 0; j < KL; j++) {
        const float wv = wrow[j];            // scalar warp-uniform LDS
        #pragma unroll
        for (int t = 0; t < WIDE; t++)
            accL[t] = fmaf(xw[(j + t) & 15], wv, accL[t]);
        if (j >= 13 && j <= 17) {            // fused 5x5 taps, same operands
            const float sv = wsr[j - 13];
            #pragma unroll
            for (int t = 0; t < WIDE; t++)
                accS[t] = fmaf(xw[(j + t) & 15], sv, accS[t]);
        }
        if ((j & 1) && j <= 27) {            // paired window refill (even addr)
            float2 v = *(const float2*)&xr[j + 15];
            xw[(j + 15) & 15] = v.x;
            xw[(j + 16) & 15] = v.y;
        }
    }
}

__global__ __launch_bounds__(NTHR, 4) void k_conv(const float* __restrict__ x,
                                                  const float* __restrict__ wl_g,
                                                  const float* __restrict__ ws_g) {
    __shared__ __align__(16) float tile[TILE_PAD];
    __shared__ __align__(16) float wlp[KL * 32];   // weight rows padded to 32
    __shared__ float ws[32];
    __shared__ float red[7 * 4];

    const int blk = blockIdx.x;          // n*C + c
    const int c   = blk % C_;
    const int tid = threadIdx.x;
    const float* img = x + (size_t)blk * HW_;

    const int row   = tid % 56;          // output row / interior row
    const int strip = tid / 56;          // 0..3
    const int col0  = strip * WIDE;      // 0, 14, 28, 42 (all even)

    // ---- phase 1: zero full padded tile (float4), load weights ----
    #pragma unroll
    for (int u = 0; u < TILE_PAD / 4; u += NTHR) {
        int idx = u + tid;
        if (idx < TILE_PAD / 4) ((float4*)tile)[idx] = make_float4(0.f, 0.f, 0.f, 0.f);
    }
    for (int idx = tid; idx < KL * 32; idx += NTHR) {
        int i = idx >> 5, j = idx & 31;
        wlp[idx] = (j < KL) ? wl_g[c * KL * KL + i * KL + j] : 0.f;
    }
    if (tid < KS * KS) ws[tid] = ws_g[c * KS * KS + tid];
    __syncthreads();

    // ---- phase 2: interior load, exact fit: thread = (row, 14-col strip) ----
    {
        const float* src = img + row * W_ + col0;   // even offset -> 8B aligned
        float* dst = &tile[(row + PL) * STR + PL + col0];
        #pragma unroll
        for (int t = 0; t < WIDE; t += 2) {
            float2 v = *(const float2*)&src[t];
            dst[t]     = v.x;
            dst[t + 1] = v.y;
        }
    }
    __syncthreads();

    const size_t ob = (size_t)blk * HW_ + (size_t)row * W_ + col0;
    float sL = 0.f, qL = 0.f, sS = 0.f, qS = 0.f;

    // ---- fused 31x31 + 5x5 depthwise conv ----
    {
        float accL[WIDE];
        #pragma unroll
        for (int t = 0; t < WIDE; t++) accL[t] = 0.f;

        #pragma unroll 1
        for (int i = 0; i < 13; i++)
            conv_row_main(&tile[(row + i) * STR + col0],
                          (const float4*)&wlp[i * 32], accL);

        // 5x5 lives entirely in rows 13..17: accS scoped to this segment only
        {
            float accS[WIDE];
            #pragma unroll
            for (int t = 0; t < WIDE; t++) accS[t] = 0.f;

            #pragma unroll 1
            for (int i = 13; i < 18; i++)
                conv_row_fuse(&tile[(row + i) * STR + col0],
                              &wlp[i * 32], &ws[(i - 13) * KS], accL, accS);

            #pragma unroll
            for (int t = 0; t < WIDE; t += 2)
                *(float2*)&g_ys[ob + t] = make_float2(accS[t], accS[t+1]);
            #pragma unroll
            for (int t = 0; t < WIDE; t++) {
                sS += accS[t]; qS = fmaf(accS[t], accS[t], qS);
            }
        }

        #pragma unroll 1
        for (int i = 18; i < KL; i++)
            conv_row_main(&tile[(row + i) * STR + col0],
                          (const float4*)&wlp[i * 32], accL);

        #pragma unroll
        for (int t = 0; t < WIDE; t += 2)
            *(float2*)&g_yl[ob + t] = make_float2(accL[t], accL[t+1]);
        #pragma unroll
        for (int t = 0; t < WIDE; t++) {
            sL += accL[t]; qL = fmaf(accL[t], accL[t], qL);
        }
    }

    // ---- block reduction of the 4 stats (7 warps) ----
    #pragma unroll
    for (int o = 16; o; o >>= 1) {
        sL += __shfl_down_sync(0xffffffffu, sL, o);
        qL += __shfl_down_sync(0xffffffffu, qL, o);
        sS += __shfl_down_sync(0xffffffffu, sS, o);
        qS += __shfl_down_sync(0xffffffffu, qS, o);
    }
    const int lane = tid & 31, wpid = tid >> 5;
    if (lane == 0) { red[wpid*4+0]=sL; red[wpid*4+1]=qL; red[wpid*4+2]=sS; red[wpid*4+3]=qS; }
    __syncthreads();
    if (tid < 4) {
        float v = 0.f;
        #pragma unroll
        for (int ww = 0; ww < 7; ww++) v += red[ww * 4 + tid];
        atomicAdd(&g_acc[c * 4 + tid], v);
    }
}

__global__ void k_stats(const float* __restrict__ gL, const float* __restrict__ bL,
                        const float* __restrict__ gS, const float* __restrict__ bS) {
    int c = blockIdx.x * blockDim.x + threadIdx.x;
    if (c >= C_) return;
    const float inv_n = 1.f / (float)NHW_;
    float mL = g_acc[c*4+0] * inv_n;
    float vL = g_acc[c*4+1] * inv_n - mL * mL;
    float aL = gL[c] * rsqrtf(vL + 1e-5f);
    float mS = g_acc[c*4+2] * inv_n;
    float vS = g_acc[c*4+3] * inv_n - mS * mS;
    float aS = gS[c] * rsqrtf(vS + 1e-5f);
    g_prm[c]        = aL;
    g_prm[C_ + c]   = aS;
    g_prm[2*C_ + c] = bL[c] - mL * aL + bS[c] - mS * aS;
}

__global__ __launch_bounds__(256) void k_out(float* __restrict__ out) {
    int i = blockIdx.x * blockDim.x + threadIdx.x;
    if (i >= TOT_ / 4) return;
    int e = i * 4;
    int c = (e / HW_) % C_;          // HW_ divisible by 4 -> channel constant in float4
    float aL = g_prm[c], aS = g_prm[C_ + c], bb = g_prm[2*C_ + c];
    float4 l = ((const float4*)g_yl)[i];
    float4 s = ((const float4*)g_ys)[i];
    float4 o;
    o.x = fmaf(aL, l.x, fmaf(aS, s.x, bb));
    o.y = fmaf(aL, l.y, fmaf(aS, s.y, bb));
    o.z = fmaf(aL, l.z, fmaf(aS, s.z, bb));
    o.w = fmaf(aL, l.w, fmaf(aS, s.w, bb));
    ((float4*)out)[i] = o;
}

extern "C" void kernel_launch(void* const* d_in, const int* in_sizes, int n_in,
                              void* d_out, int out_size) {
    const float* x  = (const float*)d_in[0];
    const float* wl = (const float*)d_in[1];
    const float* gl = (const float*)d_in[2];
    const float* bl = (const float*)d_in[3];
    const float* ws = (const float*)d_in[4];
    const float* gs = (const float*)d_in[5];
    const float* bs = (const float*)d_in[6];

    k_zero<<<6, 256>>>();
    k_conv<<<B_ * C_, NTHR>>>(x, wl, ws);
    k_stats<<<2, 192>>>(gl, bl, gs, bs);
    k_out<<<(TOT_ / 4 + 255) / 256, 256>>>((float*)d_out);
}